// round 4
// baseline (speedup 1.0000x reference)
#include <cuda_runtime.h>
#include <cuda_bf16.h>
#include <mma.h>
#include <math_constants.h>

#define NPTS 4096
#define DDATA 1024
#define DLAT 64
#define NEDGE (NPTS - 1)
#define ROUNDS 12

using namespace nvcuda;

// ---- scratch (no allocations allowed: device globals) ----
static __device__ float g_ddist[(size_t)NPTS * NPTS];
static __device__ float g_ldist[(size_t)NPTS * NPTS];
static __device__ __nv_bfloat16 g_a16[(size_t)NPTS * (3 * DDATA)];   // [hi|lo|hi]
static __device__ __nv_bfloat16 g_b16[(size_t)NPTS * (3 * DDATA)];   // [hi|hi|lo]
static __device__ __nv_bfloat16 g_al16[(size_t)NPTS * (3 * DLAT)];
static __device__ __nv_bfloat16 g_bl16[(size_t)NPTS * (3 * DLAT)];
static __device__ float g_sqd[NPTS];
static __device__ float g_sql[NPTS];
static __device__ float g_ae[NPTS];
static __device__ int   g_edges[2][NEDGE * 2];
static __device__ int   g_ecnt[2];
static __device__ int   g_done[2];
static __device__ int   g_comp[2][NPTS];
static __device__ int   g_parent[2][NPTS];
static __device__ unsigned long long g_nbest[2][NPTS];
static __device__ unsigned g_dmax_bits;
static __device__ float g_topo;

__global__ void init_kernel() {
    int i = blockIdx.x * blockDim.x + threadIdx.x;
    if (i < NPTS) { g_comp[0][i] = i; g_comp[1][i] = i; }
    if (i == 0) {
        g_dmax_bits = 0u;
        g_ecnt[0] = 0; g_ecnt[1] = 0;
        g_done[0] = 0; g_done[1] = 0;
    }
}

// ---- AE loss + squared norms of y_true (one block per row) ----
__global__ void __launch_bounds__(256) ae_sq_kernel(
    const float* __restrict__ yt, const float* __restrict__ yp) {
    int row = blockIdx.x, tid = threadIdx.x;
    float4 a = ((const float4*)(yt + (size_t)row * DDATA))[tid];
    float4 b = ((const float4*)(yp + (size_t)row * DDATA))[tid];
    float dx = a.x - b.x, dy = a.y - b.y, dz = a.z - b.z, dw = a.w - b.w;
    float ae = dx * dx + dy * dy + dz * dz + dw * dw;
    float sq = a.x * a.x + a.y * a.y + a.z * a.z + a.w * a.w;
#pragma unroll
    for (int off = 16; off; off >>= 1) {
        ae += __shfl_down_sync(0xffffffffu, ae, off);
        sq += __shfl_down_sync(0xffffffffu, sq, off);
    }
    __shared__ float sae[8], ssq[8];
    if ((tid & 31) == 0) { sae[tid >> 5] = ae; ssq[tid >> 5] = sq; }
    __syncthreads();
    if (tid < 8) {
        ae = sae[tid]; sq = ssq[tid];
#pragma unroll
        for (int off = 4; off; off >>= 1) {
            ae += __shfl_down_sync(0xffu, ae, off);
            sq += __shfl_down_sync(0xffu, sq, off);
        }
        if (tid == 0) { g_ae[row] = ae * (1.0f / DDATA); g_sqd[row] = sq; }
    }
}

// ---- squared norms of latent rows (one warp per row) ----
__global__ void __launch_bounds__(32) sq_lat_kernel(const float* __restrict__ lat) {
    int row = blockIdx.x, tid = threadIdx.x;
    float2 v = ((const float2*)(lat + (size_t)row * DLAT))[tid];
    float s = v.x * v.x + v.y * v.y;
#pragma unroll
    for (int off = 16; off; off >>= 1) s += __shfl_down_sync(0xffffffffu, s, off);
    if (tid == 0) g_sql[row] = s;
}

// ---- split fp32 -> [hi|lo|hi] / [hi|hi|lo] bf16 arrays ----
__global__ void __launch_bounds__(256) split_kernel(
    const float* __restrict__ X, __nv_bfloat16* __restrict__ A,
    __nv_bfloat16* __restrict__ B, int K) {
    int idx = blockIdx.x * blockDim.x + threadIdx.x;       // per float2
    int half = K >> 1;
    int i = idx / half;
    int kk = (idx - i * half) * 2;
    float2 x = *(const float2*)(X + (size_t)i * K + kk);
    __nv_bfloat16 h0 = __float2bfloat16(x.x);
    __nv_bfloat16 h1 = __float2bfloat16(x.y);
    __nv_bfloat16 l0 = __float2bfloat16(x.x - __bfloat162float(h0));
    __nv_bfloat16 l1 = __float2bfloat16(x.y - __bfloat162float(h1));
    __nv_bfloat162 hi = __nv_bfloat162(h0, h1);
    __nv_bfloat162 lo = __nv_bfloat162(l0, l1);
    size_t base = (size_t)i * (3 * K) + kk;
    *(__nv_bfloat162*)(A + base)         = hi;
    *(__nv_bfloat162*)(A + base + K)     = lo;
    *(__nv_bfloat162*)(A + base + 2 * K) = hi;
    *(__nv_bfloat162*)(B + base)         = hi;
    *(__nv_bfloat162*)(B + base + K)     = hi;
    *(__nv_bfloat162*)(B + base + 2 * K) = lo;
}

// ---- tensor-core gram -> Euclidean distance matrix ----
// 128x128 tile, 8 warps (warp tile 32x64), bf16 wmma m16n16k16, KC=32.
#define SLD 40   // smem row stride in bf16 elems (80B, mult of 16B)
template<int KTOT>
__global__ void __launch_bounds__(256, 2) gram16_kernel(
    const __nv_bfloat16* __restrict__ Ag,
    const __nv_bfloat16* __restrict__ Bg, int which) {
    int bj = blockIdx.x, bi = blockIdx.y;
    if (bi > bj) return;

    __shared__ __nv_bfloat16 As[128 * SLD];
    __shared__ __nv_bfloat16 Bs[128 * SLD];

    int tid = threadIdx.x;
    int wid = tid >> 5, lane = tid & 31;
    int wm = wid & 3;        // m offset = wm*32
    int wn = wid >> 2;       // n offset = wn*64

    wmma::fragment<wmma::accumulator, 16, 16, 16, float> acc[2][4];
#pragma unroll
    for (int mi = 0; mi < 2; mi++)
#pragma unroll
        for (int ni = 0; ni < 4; ni++) wmma::fill_fragment(acc[mi][ni], 0.0f);

    int row = tid >> 2;                 // 0..63
    int col8 = (tid & 3) << 3;          // 0,8,16,24
    const __nv_bfloat16* Ap = Ag + (size_t)(bi * 128 + row) * KTOT + col8;
    const __nv_bfloat16* Bp = Bg + (size_t)(bj * 128 + row) * KTOT + col8;
    size_t rstride = (size_t)64 * KTOT;

    uint4 ra0 = *(const uint4*)(Ap);
    uint4 ra1 = *(const uint4*)(Ap + rstride);
    uint4 rb0 = *(const uint4*)(Bp);
    uint4 rb1 = *(const uint4*)(Bp + rstride);

#pragma unroll 1
    for (int k0 = 0; k0 < KTOT; k0 += 32) {
        *(uint4*)(As + row * SLD + col8)        = ra0;
        *(uint4*)(As + (row + 64) * SLD + col8) = ra1;
        *(uint4*)(Bs + row * SLD + col8)        = rb0;
        *(uint4*)(Bs + (row + 64) * SLD + col8) = rb1;
        __syncthreads();

        uint4 na0, na1, nb0, nb1;
        if (k0 + 32 < KTOT) {
            na0 = *(const uint4*)(Ap + k0 + 32);
            na1 = *(const uint4*)(Ap + rstride + k0 + 32);
            nb0 = *(const uint4*)(Bp + k0 + 32);
            nb1 = *(const uint4*)(Bp + rstride + k0 + 32);
        }

#pragma unroll
        for (int kk = 0; kk < 32; kk += 16) {
            wmma::fragment<wmma::matrix_a, 16, 16, 16, __nv_bfloat16, wmma::row_major> af[2];
            wmma::fragment<wmma::matrix_b, 16, 16, 16, __nv_bfloat16, wmma::col_major> bf[4];
#pragma unroll
            for (int mi = 0; mi < 2; mi++)
                wmma::load_matrix_sync(af[mi], As + (wm * 32 + mi * 16) * SLD + kk, SLD);
#pragma unroll
            for (int ni = 0; ni < 4; ni++)
                wmma::load_matrix_sync(bf[ni], Bs + (wn * 64 + ni * 16) * SLD + kk, SLD);
#pragma unroll
            for (int mi = 0; mi < 2; mi++)
#pragma unroll
                for (int ni = 0; ni < 4; ni++)
                    wmma::mma_sync(acc[mi][ni], af[mi], bf[ni], acc[mi][ni]);
        }
        __syncthreads();
        ra0 = na0; ra1 = na1; rb0 = nb0; rb1 = nb1;
    }

    // epilogue: reuse As as per-warp float staging (8 warps x 256 floats = 8KB)
    const float* __restrict__ sq = (which == 0) ? g_sqd : g_sql;
    float* __restrict__ D = (which == 0) ? g_ddist : g_ldist;
    float* sc = (float*)As;
    float lmax = 0.f;
#pragma unroll
    for (int mi = 0; mi < 2; mi++) {
#pragma unroll
        for (int ni = 0; ni < 4; ni++) {
            wmma::store_matrix_sync(sc + wid * 256, acc[mi][ni], 16, wmma::mem_row_major);
            __syncwarp();
            int m0 = bi * 128 + wm * 32 + mi * 16;
            int n0 = bj * 128 + wn * 64 + ni * 16;
            int r = lane >> 1;
            int c0 = (lane & 1) << 3;
            float sqa = sq[m0 + r];
#pragma unroll
            for (int t = 0; t < 8; t++) {
                int c = c0 + t;
                float g = sc[wid * 256 + r * 16 + c];
                int gi = m0 + r, gj = n0 + c;
                float d2 = sqa + sq[gj] - 2.0f * g;
                float d = (d2 > 0.f) ? sqrtf(d2) : 0.f;
                D[(size_t)gi * NPTS + gj] = d;
                if (bi != bj) D[(size_t)gj * NPTS + gi] = d;
                lmax = fmaxf(lmax, d);
            }
            __syncwarp();
        }
    }

    if (which == 0) {
#pragma unroll
        for (int off = 16; off; off >>= 1)
            lmax = fmaxf(lmax, __shfl_down_sync(0xffffffffu, lmax, off));
        __shared__ float smax[8];
        if (lane == 0) smax[wid] = lmax;
        __syncthreads();
        if (tid == 0) {
            float m = smax[0];
#pragma unroll
            for (int w = 1; w < 8; w++) m = fmaxf(m, smax[w]);
            atomicMax(&g_dmax_bits, __float_as_uint(m));
        }
    }
}

// ---- Boruvka scan: per-node min outgoing edge (one warp per row) ----
__global__ void __launch_bounds__(256) boruvka_scan() {
    int m = blockIdx.y;
    if (g_done[m]) return;
    const float* __restrict__ dist = (m == 0) ? g_ddist : g_ldist;
    const int* __restrict__ comp = g_comp[m];

    __shared__ __align__(16) int scomp[NPTS];
    for (int t = threadIdx.x; t < NPTS; t += 256) scomp[t] = comp[t];
    __syncthreads();

    int w = threadIdx.x >> 5, lane = threadIdx.x & 31;
    int row = blockIdx.x * 8 + w;
    int mycomp = scomp[row];
    const float4* __restrict__ rp = (const float4*)(dist + (size_t)row * NPTS);
    const int4* __restrict__ cp = (const int4*)scomp;

    unsigned bestv = 0xFFFFFFFFu;
    int bestj = 0;
#pragma unroll 8
    for (int k = 0; k < 32; k++) {
        int c4 = k * 32 + lane;
        float4 v = rp[c4];
        int4 cc = cp[c4];
        int col = c4 << 2;
        unsigned b;
        b = __float_as_uint(v.x); if (cc.x != mycomp && b < bestv) { bestv = b; bestj = col; }
        b = __float_as_uint(v.y); if (cc.y != mycomp && b < bestv) { bestv = b; bestj = col + 1; }
        b = __float_as_uint(v.z); if (cc.z != mycomp && b < bestv) { bestv = b; bestj = col + 2; }
        b = __float_as_uint(v.w); if (cc.w != mycomp && b < bestv) { bestv = b; bestj = col + 3; }
    }
    unsigned rv = __reduce_min_sync(0xffffffffu, bestv);
    unsigned rj = __reduce_min_sync(0xffffffffu,
                                    (bestv == rv) ? (unsigned)bestj : 0xFFFFFFFFu);
    if (lane == 0)
        g_nbest[m][row] = ((unsigned long long)rv << 24)
                        | ((unsigned long long)row << 12)
                        | (unsigned long long)rj;
}

// ---- Boruvka merge: per-comp best, hook, pointer-jump, relabel ----
__global__ void __launch_bounds__(1024) boruvka_merge() {
    int m = blockIdx.x;
    if (g_done[m]) return;
    __shared__ __align__(8) unsigned long long table[NPTS];
    __shared__ int scnt;
    int tid = threadIdx.x;
    int* __restrict__ parent = g_parent[m];
    const int* __restrict__ comp = g_comp[m];

    for (int c = tid; c < NPTS; c += 1024) { table[c] = ~0ull; parent[c] = c; }
    if (tid == 0) scnt = 0;
    __syncthreads();

    for (int n = tid; n < NPTS; n += 1024)
        atomicMin(&table[comp[n]], g_nbest[m][n]);
    __syncthreads();

    for (int c = tid; c < NPTS; c += 1024) {
        unsigned long long e = table[c];
        if (e != ~0ull) {
            int i = (int)((e >> 12) & 0xFFF);
            int j = (int)(e & 0xFFF);
            int t = comp[j];
            unsigned long long et = table[t];
            int i2 = (int)((et >> 12) & 0xFFF);
            int j2 = (int)(et & 0xFFF);
            bool mutual = (i2 == j) && (j2 == i);
            if (!mutual || c < t) {
                int pos = atomicAdd(&g_ecnt[m], 1);
                g_edges[m][2 * pos]     = i;
                g_edges[m][2 * pos + 1] = j;
            }
            parent[c] = (mutual && c < t) ? c : t;
        }
    }
    __syncthreads();

    for (int it = 0; it < 12; it++) {
        for (int c = tid; c < NPTS; c += 1024) {
            int p = parent[c];
            parent[c] = parent[p];
        }
        __syncthreads();
    }

    int* mark = (int*)table;
    for (int c = tid; c < NPTS; c += 1024) mark[c] = 0;
    __syncthreads();
    for (int n = tid; n < NPTS; n += 1024) {
        int r = parent[comp[n]];
        g_comp[m][n] = r;
        mark[r] = 1;
    }
    __syncthreads();
    int cnt = 0;
    for (int c = tid; c < NPTS; c += 1024) cnt += mark[c];
#pragma unroll
    for (int off = 16; off; off >>= 1) cnt += __shfl_down_sync(0xffffffffu, cnt, off);
    if ((tid & 31) == 0) atomicAdd(&scnt, cnt);
    __syncthreads();
    if (tid == 0 && scnt == 1) g_done[m] = 1;
}

// ---- gather MST edges, compute topo loss ----
__global__ void __launch_bounds__(1024) topo_kernel(const float* __restrict__ lnorm) {
    int tid = threadIdx.x;
    float invmax = 1.0f / __uint_as_float(g_dmax_bits);
    float invln = 1.0f / lnorm[0];
    float sd = 0.f, sl = 0.f;
    for (int e = tid; e < NEDGE; e += 1024) {
        int u = g_edges[0][2 * e], v = g_edges[0][2 * e + 1];
        size_t o = (size_t)u * NPTS + v;
        float t = g_ddist[o] * invmax - g_ldist[o] * invln;
        sd += t * t;
        u = g_edges[1][2 * e]; v = g_edges[1][2 * e + 1];
        o = (size_t)u * NPTS + v;
        t = g_ddist[o] * invmax - g_ldist[o] * invln;
        sl += t * t;
    }
#pragma unroll
    for (int off = 16; off; off >>= 1) {
        sd += __shfl_down_sync(0xffffffffu, sd, off);
        sl += __shfl_down_sync(0xffffffffu, sl, off);
    }
    __shared__ float ssd[32], ssl[32];
    if ((tid & 31) == 0) { ssd[tid >> 5] = sd; ssl[tid >> 5] = sl; }
    __syncthreads();
    if (tid < 32) {
        sd = ssd[tid]; sl = ssl[tid];
#pragma unroll
        for (int off = 16; off; off >>= 1) {
            sd += __shfl_down_sync(0xffffffffu, sd, off);
            sl += __shfl_down_sync(0xffffffffu, sl, off);
        }
        if (tid == 0) g_topo = (sd + sl) * (1.0f / NEDGE);
    }
}

__global__ void final_kernel(float* __restrict__ out) {
    int i = blockIdx.x * blockDim.x + threadIdx.x;
    if (i < NPTS) out[i] = g_ae[i] + 0.5f * g_topo;
}

extern "C" void kernel_launch(void* const* d_in, const int* in_sizes, int n_in,
                              void* d_out, int out_size) {
    const float* y_true      = (const float*)d_in[0];
    const float* latent      = (const float*)d_in[1];
    const float* y_pred      = (const float*)d_in[2];
    const float* latent_norm = (const float*)d_in[3];
    float* out = (float*)d_out;

    init_kernel<<<16, 256>>>();
    ae_sq_kernel<<<NPTS, 256>>>(y_true, y_pred);
    sq_lat_kernel<<<NPTS, 32>>>(latent);
    split_kernel<<<(NPTS * DDATA / 2) / 256, 256>>>(y_true, g_a16, g_b16, DDATA);
    split_kernel<<<(NPTS * DLAT / 2) / 256, 256>>>(latent, g_al16, g_bl16, DLAT);
    dim3 grid(32, 32);
    gram16_kernel<3 * DDATA><<<grid, 256>>>(g_a16, g_b16, 0);
    gram16_kernel<3 * DLAT><<<grid, 256>>>(g_al16, g_bl16, 1);
    for (int r = 0; r < ROUNDS; r++) {
        boruvka_scan<<<dim3(512, 2), 256>>>();
        boruvka_merge<<<2, 1024>>>();
    }
    topo_kernel<<<1, 1024>>>(latent_norm);
    final_kernel<<<16, 256>>>(out);
}